// round 9
// baseline (speedup 1.0000x reference)
#include <cuda_runtime.h>
#include <cuda_fp16.h>
#include <mma.h>
#include <math.h>

using namespace nvcuda;

// Problem constants
#define B_  4
#define S_  2048
#define E_  1024
#define H_  16
#define DH_ 64
#define M_  (B_ * S_)
#define OUT_ELEMS ((size_t)B_ * S_ * E_)

// Scratch (device globals: allocation-free per harness rules)
__device__ float g_Q[M_ * E_];
__device__ float g_K[M_ * E_];
__device__ float g_V[M_ * E_];
__device__ float g_O[M_ * E_];

typedef wmma::fragment<wmma::matrix_a, 16, 16, 16, __half, wmma::row_major> HA;
typedef wmma::fragment<wmma::matrix_b, 16, 16, 16, __half, wmma::col_major> HBc;
typedef wmma::fragment<wmma::matrix_b, 16, 16, 16, __half, wmma::row_major> HBr;
typedef wmma::fragment<wmma::accumulator, 16, 16, 16, float> HC;

__device__ __forceinline__ void split1(float x, __half* h, __half* l) {
    __half hh = __float2half_rn(x);
    *h = hh;
    *l = __float2half_rn(x - __half2float(hh));
}

// ---------------------------------------------------------------------------
// NT GEMM, fp16x2 compensated: C[M,N] = A[M,K] @ W[N,K]^T + bias[N]
// BM=BN=128, BK=32, 256 threads = 8 warps (2x4), warp tile 64x32.
// ---------------------------------------------------------------------------
__global__ void __launch_bounds__(256) gemm_nt_fp16x2(
    const float* __restrict__ A, const float* __restrict__ W,
    const float* __restrict__ bias, float* __restrict__ C,
    int Mdim, int Ndim, int Kdim)
{
    __shared__ __align__(128) __half Ah[128 * 32];
    __shared__ __align__(128) __half Al[128 * 32];
    __shared__ __align__(128) __half Bh[128 * 32];
    __shared__ __align__(128) __half Bl[128 * 32];
    __shared__ __align__(128) float stage[8][256];

    const int tid = threadIdx.x;
    const int w = tid >> 5, lane = tid & 31;
    const int m0 = blockIdx.y * 128, n0 = blockIdx.x * 128;
    const int wm = w & 1;     // rows wm*64
    const int wn = w >> 1;    // cols wn*32

    HC acc[4][2];
#pragma unroll
    for (int fm = 0; fm < 4; fm++)
#pragma unroll
        for (int fn = 0; fn < 2; fn++) wmma::fill_fragment(acc[fm][fn], 0.0f);

    const int r = tid >> 1;
    const int cb = (tid & 1) * 16;

    for (int k0 = 0; k0 < Kdim; k0 += 32) {
#pragma unroll
        for (int i = 0; i < 4; i++) {
            int c = cb + i * 4;
            float4 a4 = *(const float4*)&A[(size_t)(m0 + r) * Kdim + k0 + c];
            int o = r * 32 + c;
            split1(a4.x, &Ah[o + 0], &Al[o + 0]);
            split1(a4.y, &Ah[o + 1], &Al[o + 1]);
            split1(a4.z, &Ah[o + 2], &Al[o + 2]);
            split1(a4.w, &Ah[o + 3], &Al[o + 3]);
            float4 b4 = *(const float4*)&W[(size_t)(n0 + r) * Kdim + k0 + c];
            split1(b4.x, &Bh[o + 0], &Bl[o + 0]);
            split1(b4.y, &Bh[o + 1], &Bl[o + 1]);
            split1(b4.z, &Bh[o + 2], &Bl[o + 2]);
            split1(b4.w, &Bh[o + 3], &Bl[o + 3]);
        }
        __syncthreads();

#pragma unroll
        for (int ks = 0; ks < 2; ks++) {
            const int kk = ks * 16;
            HA ah[4], al[4];
            HBc bh[2], bl[2];
#pragma unroll
            for (int fm = 0; fm < 4; fm++) {
                wmma::load_matrix_sync(ah[fm], &Ah[(wm * 64 + fm * 16) * 32 + kk], 32);
                wmma::load_matrix_sync(al[fm], &Al[(wm * 64 + fm * 16) * 32 + kk], 32);
            }
#pragma unroll
            for (int fn = 0; fn < 2; fn++) {
                wmma::load_matrix_sync(bh[fn], &Bh[(wn * 32 + fn * 16) * 32 + kk], 32);
                wmma::load_matrix_sync(bl[fn], &Bl[(wn * 32 + fn * 16) * 32 + kk], 32);
            }
#pragma unroll
            for (int fm = 0; fm < 4; fm++)
#pragma unroll
                for (int fn = 0; fn < 2; fn++) {
                    wmma::mma_sync(acc[fm][fn], ah[fm], bh[fn], acc[fm][fn]);
                    wmma::mma_sync(acc[fm][fn], ah[fm], bl[fn], acc[fm][fn]);
                    wmma::mma_sync(acc[fm][fn], al[fm], bh[fn], acc[fm][fn]);
                }
        }
        __syncthreads();
    }

    // Epilogue: per-warp smem stage, add bias, coalesced float4 stores
    const int er = lane >> 1;
    const int ec = (lane & 1) * 8;
#pragma unroll
    for (int fm = 0; fm < 4; fm++)
#pragma unroll
        for (int fn = 0; fn < 2; fn++) {
            wmma::store_matrix_sync(&stage[w][0], acc[fm][fn], 16, wmma::mem_row_major);
            __syncwarp();
            int gm = m0 + wm * 64 + fm * 16 + er;
            int gn = n0 + wn * 32 + fn * 16 + ec;
            float4 s0 = *(float4*)&stage[w][er * 16 + ec];
            float4 s1 = *(float4*)&stage[w][er * 16 + ec + 4];
            float4 b0 = *(const float4*)&bias[gn];
            float4 b1 = *(const float4*)&bias[gn + 4];
            s0.x += b0.x; s0.y += b0.y; s0.z += b0.z; s0.w += b0.w;
            s1.x += b1.x; s1.y += b1.y; s1.z += b1.z; s1.w += b1.w;
            *(float4*)&C[(size_t)gm * Ndim + gn]     = s0;
            *(float4*)&C[(size_t)gm * Ndim + gn + 4] = s1;
            __syncwarp();
        }
}

// ---------------------------------------------------------------------------
// Fused attention: per (bh, q-block of 128):
//   pass 1: S = (Q*0.125)K^T tile-by-tile (fp16x2), online row max m + sum l
//   pass 2: recompute S, P = exp(S-m)/l -> write attn gmem + accumulate P@V
// Also zero-fills attn[q, j > q].
// ---------------------------------------------------------------------------
#define SLD 132          // padded S stride (floats)
// dynamic smem layout (bytes)
#define SM_QH   0
#define SM_QL   (SM_QH + 128*64*2)
#define SM_KVH  (SM_QL + 128*64*2)
#define SM_KVL  (SM_KVH + 128*64*2)
#define SM_S    (SM_KVL + 128*64*2)
#define SM_PH   (SM_S  + 128*SLD*4)
#define SM_PL   (SM_PH + 128*128*2)
#define SM_M    (SM_PL + 128*128*2)
#define SM_L    (SM_M + 128*4)
#define SM_FUSED_TOTAL (SM_L + 128*4)

__device__ __forceinline__ void load_split_128x64(
    const float* __restrict__ src, float scale, __half* h, __half* l, int tid)
{
    const int r = tid >> 1, cb = (tid & 1) * 32;
    const float* row = src + (size_t)r * E_ + cb;
#pragma unroll
    for (int i = 0; i < 8; i++) {
        float4 v = *(const float4*)(row + i * 4);
        int o = r * 64 + cb + i * 4;
        float x;
        x = v.x * scale; split1(x, &h[o + 0], &l[o + 0]);
        x = v.y * scale; split1(x, &h[o + 1], &l[o + 1]);
        x = v.z * scale; split1(x, &h[o + 2], &l[o + 2]);
        x = v.w * scale; split1(x, &h[o + 3], &l[o + 3]);
    }
}

__device__ __forceinline__ void mma_qk_tile(
    const __half* Qh, const __half* Ql, const __half* Kh, const __half* Kl,
    int wm, int wn, HC acc[4][2])
{
#pragma unroll
    for (int fm = 0; fm < 4; fm++)
#pragma unroll
        for (int fn = 0; fn < 2; fn++) wmma::fill_fragment(acc[fm][fn], 0.0f);
#pragma unroll
    for (int ks = 0; ks < 4; ks++) {
        const int kk = ks * 16;
        HA ah[4], al[4];
        HBc bh[2], bl[2];
#pragma unroll
        for (int fm = 0; fm < 4; fm++) {
            wmma::load_matrix_sync(ah[fm], &Qh[(wm * 64 + fm * 16) * 64 + kk], 64);
            wmma::load_matrix_sync(al[fm], &Ql[(wm * 64 + fm * 16) * 64 + kk], 64);
        }
#pragma unroll
        for (int fn = 0; fn < 2; fn++) {
            wmma::load_matrix_sync(bh[fn], &Kh[(wn * 32 + fn * 16) * 64 + kk], 64);
            wmma::load_matrix_sync(bl[fn], &Kl[(wn * 32 + fn * 16) * 64 + kk], 64);
        }
#pragma unroll
        for (int fm = 0; fm < 4; fm++)
#pragma unroll
            for (int fn = 0; fn < 2; fn++) {
                wmma::mma_sync(acc[fm][fn], ah[fm], bh[fn], acc[fm][fn]);
                wmma::mma_sync(acc[fm][fn], ah[fm], bl[fn], acc[fm][fn]);
                wmma::mma_sync(acc[fm][fn], al[fm], bh[fn], acc[fm][fn]);
            }
    }
}

__global__ void __launch_bounds__(256) fused_attn(
    const float* __restrict__ Qp, const float* __restrict__ Kp,
    const float* __restrict__ Vp, float* __restrict__ attn,
    float* __restrict__ O)
{
    extern __shared__ __align__(128) char sm[];
    __half* Qh  = (__half*)(sm + SM_QH);
    __half* Ql  = (__half*)(sm + SM_QL);
    __half* KVh = (__half*)(sm + SM_KVH);
    __half* KVl = (__half*)(sm + SM_KVL);
    float*  Ssm = (float*)(sm + SM_S);
    __half* Ph  = (__half*)(sm + SM_PH);
    __half* Pl  = (__half*)(sm + SM_PL);
    float*  m_s = (float*)(sm + SM_M);
    float*  l_s = (float*)(sm + SM_L);

    const int qt = (gridDim.x - 1) - blockIdx.x;   // heavy blocks first
    const int bh = blockIdx.y;
    const int b = bh >> 4;
    const int h = bh & 15;
    const int q0 = qt * 128;

    const int tid = threadIdx.x;
    const int w = tid >> 5;
    const int wm = w & 1, wn = w >> 1;   // S-tile warp layout (2x4)
    const int om = w >> 1, on = w & 1;   // O-tile warp layout (4x2)

    // Load + split Q block (scaled by 1/sqrt(DH))
    load_split_128x64(Qp + ((size_t)b * S_ + q0) * E_ + h * DH_, 0.125f, Qh, Ql, tid);
    if (tid < 128) { m_s[tid] = -INFINITY; l_s[tid] = 0.f; }
    __syncthreads();

    const int sr = tid >> 1;           // stats: row
    const int sh = tid & 1;            // stats: which half (64 cols)
    float* attn_base = attn + (size_t)bh * S_ * S_;

    // ---------------- Pass 1: row max + exp-sum ----------------
    for (int jt = 0; jt <= qt; jt++) {
        const int j0 = jt * 128;
        load_split_128x64(Kp + ((size_t)b * S_ + j0) * E_ + h * DH_, 1.0f, KVh, KVl, tid);
        __syncthreads();

        HC acc[4][2];
        mma_qk_tile(Qh, Ql, KVh, KVl, wm, wn, acc);
#pragma unroll
        for (int fm = 0; fm < 4; fm++)
#pragma unroll
            for (int fn = 0; fn < 2; fn++)
                wmma::store_matrix_sync(
                    &Ssm[(wm * 64 + fm * 16) * SLD + wn * 32 + fn * 16],
                    acc[fm][fn], SLD, wmma::mem_row_major);
        __syncthreads();

        // row stats (2 threads per row)
        const bool diag = (jt == qt);
        const int cbase = sh * 64;
        float tmax = -INFINITY;
#pragma unroll 4
        for (int g = 0; g < 16; g++) {
            float4 s4 = *(float4*)&Ssm[sr * SLD + cbase + g * 4];
            int c = cbase + g * 4;
            if (!diag || c + 0 <= sr) tmax = fmaxf(tmax, s4.x);
            if (!diag || c + 1 <= sr) tmax = fmaxf(tmax, s4.y);
            if (!diag || c + 2 <= sr) tmax = fmaxf(tmax, s4.z);
            if (!diag || c + 3 <= sr) tmax = fmaxf(tmax, s4.w);
        }
        tmax = fmaxf(tmax, __shfl_xor_sync(0xffffffffu, tmax, 1));
        const float m_old = m_s[sr];
        const float m_new = fmaxf(m_old, tmax);
        float part = 0.f;
#pragma unroll 4
        for (int g = 0; g < 16; g++) {
            float4 s4 = *(float4*)&Ssm[sr * SLD + cbase + g * 4];
            int c = cbase + g * 4;
            if (!diag || c + 0 <= sr) part += __expf(s4.x - m_new);
            if (!diag || c + 1 <= sr) part += __expf(s4.y - m_new);
            if (!diag || c + 2 <= sr) part += __expf(s4.z - m_new);
            if (!diag || c + 3 <= sr) part += __expf(s4.w - m_new);
        }
        part += __shfl_xor_sync(0xffffffffu, part, 1);
        if (sh == 0) {
            l_s[sr] = l_s[sr] * __expf(m_old - m_new) + part;
            m_s[sr] = m_new;
        }
        __syncthreads();
    }

    if (tid < 128) l_s[tid] = 1.0f / l_s[tid];
    __syncthreads();

    // ---------------- Pass 2: P = exp(S-m)/l -> gmem + P@V ----------------
    HC acco[2][2];
#pragma unroll
    for (int fm = 0; fm < 2; fm++)
#pragma unroll
        for (int fn = 0; fn < 2; fn++) wmma::fill_fragment(acco[fm][fn], 0.0f);

    for (int jt = 0; jt <= qt; jt++) {
        const int j0 = jt * 128;
        load_split_128x64(Kp + ((size_t)b * S_ + j0) * E_ + h * DH_, 1.0f, KVh, KVl, tid);
        __syncthreads();

        HC acc[4][2];
        mma_qk_tile(Qh, Ql, KVh, KVl, wm, wn, acc);
#pragma unroll
        for (int fm = 0; fm < 4; fm++)
#pragma unroll
            for (int fn = 0; fn < 2; fn++)
                wmma::store_matrix_sync(
                    &Ssm[(wm * 64 + fm * 16) * SLD + wn * 32 + fn * 16],
                    acc[fm][fn], SLD, wmma::mem_row_major);
        __syncthreads();

        // transform to P: write gmem + split fp16 into Ph/Pl
        const bool diag = (jt == qt);
        const float mr = m_s[sr], il = l_s[sr];
        const int cbase = sh * 64;
#pragma unroll 4
        for (int g = 0; g < 16; g++) {
            int c = cbase + g * 4;
            float4 s4 = *(float4*)&Ssm[sr * SLD + c];
            float4 p;
            p.x = (!diag || c + 0 <= sr) ? __expf(s4.x - mr) * il : 0.f;
            p.y = (!diag || c + 1 <= sr) ? __expf(s4.y - mr) * il : 0.f;
            p.z = (!diag || c + 2 <= sr) ? __expf(s4.z - mr) * il : 0.f;
            p.w = (!diag || c + 3 <= sr) ? __expf(s4.w - mr) * il : 0.f;
            *(float4*)&attn_base[(size_t)(q0 + sr) * S_ + j0 + c] = p;
            int o = sr * 128 + c;
            split1(p.x, &Ph[o + 0], &Pl[o + 0]);
            split1(p.y, &Ph[o + 1], &Pl[o + 1]);
            split1(p.z, &Ph[o + 2], &Pl[o + 2]);
            split1(p.w, &Ph[o + 3], &Pl[o + 3]);
        }
        __syncthreads();

        // load V tile into KV buffers (K no longer needed this iteration)
        load_split_128x64(Vp + ((size_t)b * S_ + j0) * E_ + h * DH_, 1.0f, KVh, KVl, tid);
        __syncthreads();

        // O += P @ V
#pragma unroll
        for (int ks = 0; ks < 8; ks++) {
            const int kk = ks * 16;
            HA pa[2], pl2[2];
            HBr vb[2], vl2[2];
#pragma unroll
            for (int fm = 0; fm < 2; fm++) {
                wmma::load_matrix_sync(pa[fm],  &Ph[(om * 32 + fm * 16) * 128 + kk], 128);
                wmma::load_matrix_sync(pl2[fm], &Pl[(om * 32 + fm * 16) * 128 + kk], 128);
            }
#pragma unroll
            for (int fn = 0; fn < 2; fn++) {
                wmma::load_matrix_sync(vb[fn],  &KVh[kk * 64 + on * 32 + fn * 16], 64);
                wmma::load_matrix_sync(vl2[fn], &KVl[kk * 64 + on * 32 + fn * 16], 64);
            }
#pragma unroll
            for (int fm = 0; fm < 2; fm++)
#pragma unroll
                for (int fn = 0; fn < 2; fn++) {
                    wmma::mma_sync(acco[fm][fn], pa[fm], vb[fn], acco[fm][fn]);
                    wmma::mma_sync(acco[fm][fn], pa[fm], vl2[fn], acco[fm][fn]);
                    wmma::mma_sync(acco[fm][fn], pl2[fm], vb[fn], acco[fm][fn]);
                }
        }
        __syncthreads();
    }

    // zero-fill attn[q0..q0+127][q0+128 .. S)
    const int jstart = q0 + 128;
    const int Z = S_ - jstart;
    if (Z > 0) {
        const int zq = Z >> 2;  // float4s per row
        for (int t = tid; t < 128 * zq; t += 256) {
            int r = t / zq, c = (t - r * zq) * 4;
            *(float4*)&attn_base[(size_t)(q0 + r) * S_ + jstart + c] =
                make_float4(0.f, 0.f, 0.f, 0.f);
        }
    }

    // write O block (fp32, head-merged layout)
#pragma unroll
    for (int fm = 0; fm < 2; fm++)
#pragma unroll
        for (int fn = 0; fn < 2; fn++)
            wmma::store_matrix_sync(
                &O[((size_t)b * S_ + q0 + om * 32 + fm * 16) * E_ + h * DH_ + on * 32 + fn * 16],
                acco[fm][fn], E_, wmma::mem_row_major);
}

// ---------------------------------------------------------------------------
// Launch
// ---------------------------------------------------------------------------
extern "C" void kernel_launch(void* const* d_in, const int* in_sizes, int n_in,
                              void* d_out, int out_size)
{
    const float* q  = (const float*)d_in[0];
    const float* k  = (const float*)d_in[1];
    const float* v  = (const float*)d_in[2];
    const float* wq = (const float*)d_in[3];
    const float* bq = (const float*)d_in[4];
    const float* wk = (const float*)d_in[5];
    const float* bk = (const float*)d_in[6];
    const float* wv = (const float*)d_in[7];
    const float* bv = (const float*)d_in[8];
    const float* wo = (const float*)d_in[9];
    const float* bo = (const float*)d_in[10];

    float* out  = (float*)d_out;
    float* attn = (float*)d_out + OUT_ELEMS;

    float *gQ, *gK, *gV, *gO;
    cudaGetSymbolAddress((void**)&gQ, g_Q);
    cudaGetSymbolAddress((void**)&gK, g_K);
    cudaGetSymbolAddress((void**)&gV, g_V);
    cudaGetSymbolAddress((void**)&gO, g_O);

    cudaFuncSetAttribute(fused_attn, cudaFuncAttributeMaxDynamicSharedMemorySize,
                         SM_FUSED_TOTAL);

    dim3 gproj(E_ / 128, M_ / 128);   // (8, 64)
    gemm_nt_fp16x2<<<gproj, 256>>>(q, wq, bq, gQ, M_, E_, E_);
    gemm_nt_fp16x2<<<gproj, 256>>>(k, wk, bk, gK, M_, E_, E_);
    gemm_nt_fp16x2<<<gproj, 256>>>(v, wv, bv, gV, M_, E_, E_);

    dim3 gfa(S_ / 128, B_ * H_);      // (16, 64)
    fused_attn<<<gfa, 256, SM_FUSED_TOTAL>>>(gQ, gK, gV, attn, gO);

    gemm_nt_fp16x2<<<gproj, 256>>>(gO, wo, bo, out, M_, E_, E_);
}

// round 10
// speedup vs baseline: 1.3102x; 1.3102x over previous
#include <cuda_runtime.h>
#include <cuda_fp16.h>
#include <mma.h>
#include <math.h>

using namespace nvcuda;

// Problem constants
#define B_  4
#define S_  2048
#define E_  1024
#define H_  16
#define DH_ 64
#define M_  (B_ * S_)
#define OUT_ELEMS ((size_t)B_ * S_ * E_)

// Scratch (device globals: allocation-free per harness rules)
__device__ float g_Q[M_ * E_];
__device__ float g_K[M_ * E_];
__device__ float g_V[M_ * E_];
__device__ float g_O[M_ * E_];

typedef wmma::fragment<wmma::matrix_a, 16, 16, 16, __half, wmma::row_major> HA;
typedef wmma::fragment<wmma::matrix_b, 16, 16, 16, __half, wmma::col_major> HBc;
typedef wmma::fragment<wmma::matrix_b, 16, 16, 16, __half, wmma::row_major> HBr;
typedef wmma::fragment<wmma::accumulator, 16, 16, 16, float> HC;

__device__ __forceinline__ void split1(float x, __half* h, __half* l) {
    __half hh = __float2half_rn(x);
    *h = hh;
    *l = __float2half_rn(x - __half2float(hh));
}

// ---------------------------------------------------------------------------
// NT GEMM, fp16x2 compensated: C[M,N] = A[M,K] @ W[N,K]^T + bias[N]
// BM=BN=128, BK=32, 256 threads = 8 warps (2x4), warp tile 64x32. (proven R9)
// ---------------------------------------------------------------------------
__global__ void __launch_bounds__(256) gemm_nt_fp16x2(
    const float* __restrict__ A, const float* __restrict__ W,
    const float* __restrict__ bias, float* __restrict__ C,
    int Mdim, int Ndim, int Kdim)
{
    __shared__ __align__(128) __half Ah[128 * 32];
    __shared__ __align__(128) __half Al[128 * 32];
    __shared__ __align__(128) __half Bh[128 * 32];
    __shared__ __align__(128) __half Bl[128 * 32];
    __shared__ __align__(128) float stage[8][256];

    const int tid = threadIdx.x;
    const int w = tid >> 5, lane = tid & 31;
    const int m0 = blockIdx.y * 128, n0 = blockIdx.x * 128;
    const int wm = w & 1;     // rows wm*64
    const int wn = w >> 1;    // cols wn*32

    HC acc[4][2];
#pragma unroll
    for (int fm = 0; fm < 4; fm++)
#pragma unroll
        for (int fn = 0; fn < 2; fn++) wmma::fill_fragment(acc[fm][fn], 0.0f);

    const int r = tid >> 1;
    const int cb = (tid & 1) * 16;

    for (int k0 = 0; k0 < Kdim; k0 += 32) {
#pragma unroll
        for (int i = 0; i < 4; i++) {
            int c = cb + i * 4;
            float4 a4 = *(const float4*)&A[(size_t)(m0 + r) * Kdim + k0 + c];
            int o = r * 32 + c;
            split1(a4.x, &Ah[o + 0], &Al[o + 0]);
            split1(a4.y, &Ah[o + 1], &Al[o + 1]);
            split1(a4.z, &Ah[o + 2], &Al[o + 2]);
            split1(a4.w, &Ah[o + 3], &Al[o + 3]);
            float4 b4 = *(const float4*)&W[(size_t)(n0 + r) * Kdim + k0 + c];
            split1(b4.x, &Bh[o + 0], &Bl[o + 0]);
            split1(b4.y, &Bh[o + 1], &Bl[o + 1]);
            split1(b4.z, &Bh[o + 2], &Bl[o + 2]);
            split1(b4.w, &Bh[o + 3], &Bl[o + 3]);
        }
        __syncthreads();

#pragma unroll
        for (int ks = 0; ks < 2; ks++) {
            const int kk = ks * 16;
            HA ah[4], al[4];
            HBc bh[2], bl[2];
#pragma unroll
            for (int fm = 0; fm < 4; fm++) {
                wmma::load_matrix_sync(ah[fm], &Ah[(wm * 64 + fm * 16) * 32 + kk], 32);
                wmma::load_matrix_sync(al[fm], &Al[(wm * 64 + fm * 16) * 32 + kk], 32);
            }
#pragma unroll
            for (int fn = 0; fn < 2; fn++) {
                wmma::load_matrix_sync(bh[fn], &Bh[(wn * 32 + fn * 16) * 32 + kk], 32);
                wmma::load_matrix_sync(bl[fn], &Bl[(wn * 32 + fn * 16) * 32 + kk], 32);
            }
#pragma unroll
            for (int fm = 0; fm < 4; fm++)
#pragma unroll
                for (int fn = 0; fn < 2; fn++) {
                    wmma::mma_sync(acc[fm][fn], ah[fm], bh[fn], acc[fm][fn]);
                    wmma::mma_sync(acc[fm][fn], ah[fm], bl[fn], acc[fm][fn]);
                    wmma::mma_sync(acc[fm][fn], al[fm], bh[fn], acc[fm][fn]);
                }
        }
        __syncthreads();
    }

    const int er = lane >> 1;
    const int ec = (lane & 1) * 8;
#pragma unroll
    for (int fm = 0; fm < 4; fm++)
#pragma unroll
        for (int fn = 0; fn < 2; fn++) {
            wmma::store_matrix_sync(&stage[w][0], acc[fm][fn], 16, wmma::mem_row_major);
            __syncwarp();
            int gm = m0 + wm * 64 + fm * 16 + er;
            int gn = n0 + wn * 32 + fn * 16 + ec;
            float4 s0 = *(float4*)&stage[w][er * 16 + ec];
            float4 s1 = *(float4*)&stage[w][er * 16 + ec + 4];
            float4 b0 = *(const float4*)&bias[gn];
            float4 b1 = *(const float4*)&bias[gn + 4];
            s0.x += b0.x; s0.y += b0.y; s0.z += b0.z; s0.w += b0.w;
            s1.x += b1.x; s1.y += b1.y; s1.z += b1.z; s1.w += b1.w;
            *(float4*)&C[(size_t)gm * Ndim + gn]     = s0;
            *(float4*)&C[(size_t)gm * Ndim + gn + 4] = s1;
            __syncwarp();
        }
}

// ---------------------------------------------------------------------------
// Shared helper: load 128x64 fp32 head-slice, scale, split into hi/lo halves.
// ---------------------------------------------------------------------------
__device__ __forceinline__ void load_split_128x64(
    const float* __restrict__ src, float scale, __half* h, __half* l, int tid)
{
    const int r = tid >> 1, cb = (tid & 1) * 32;
    const float* row = src + (size_t)r * E_ + cb;
#pragma unroll
    for (int i = 0; i < 8; i++) {
        float4 v = *(const float4*)(row + i * 4);
        int o = r * 64 + cb + i * 4;
        float x;
        x = v.x * scale; split1(x, &h[o + 0], &l[o + 0]);
        x = v.y * scale; split1(x, &h[o + 1], &l[o + 1]);
        x = v.z * scale; split1(x, &h[o + 2], &l[o + 2]);
        x = v.w * scale; split1(x, &h[o + 3], &l[o + 3]);
    }
}

// ---------------------------------------------------------------------------
// Scores, fp16x2: raw S[q,j] = (Q*0.125) . K, 128x128 tile per block,
// causal tile skip, accumulators stored straight to gmem.
// Dynamic smem 64KB -> up to 3 CTAs/SM.
// ---------------------------------------------------------------------------
__global__ void __launch_bounds__(256) scores16(
    const float* __restrict__ Qp, const float* __restrict__ Kp,
    float* __restrict__ scores)
{
    const int jt = blockIdx.x;
    const int qt = blockIdx.y;
    if (jt > qt) return;
    const int bh = blockIdx.z;
    const int b = bh >> 4;
    const int h = bh & 15;
    const int q0 = qt * 128, j0 = jt * 128;

    extern __shared__ __align__(128) char sm[];
    __half* Qh = (__half*)sm;                       // 16KB each
    __half* Ql = (__half*)(sm + 128 * 64 * 2);
    __half* Kh = (__half*)(sm + 2 * 128 * 64 * 2);
    __half* Kl = (__half*)(sm + 3 * 128 * 64 * 2);

    const int tid = threadIdx.x;
    const int w = tid >> 5;
    const int wm = w & 1, wn = w >> 1;

    load_split_128x64(Qp + ((size_t)b * S_ + q0) * E_ + h * DH_, 0.125f, Qh, Ql, tid);
    load_split_128x64(Kp + ((size_t)b * S_ + j0) * E_ + h * DH_, 1.0f,  Kh, Kl, tid);
    __syncthreads();

    HC acc[4][2];
#pragma unroll
    for (int fm = 0; fm < 4; fm++)
#pragma unroll
        for (int fn = 0; fn < 2; fn++) wmma::fill_fragment(acc[fm][fn], 0.0f);

#pragma unroll
    for (int ks = 0; ks < 4; ks++) {
        const int kk = ks * 16;
        HA ah[4], al[4];
        HBc bh2[2], bl[2];
#pragma unroll
        for (int fm = 0; fm < 4; fm++) {
            wmma::load_matrix_sync(ah[fm], &Qh[(wm * 64 + fm * 16) * 64 + kk], 64);
            wmma::load_matrix_sync(al[fm], &Ql[(wm * 64 + fm * 16) * 64 + kk], 64);
        }
#pragma unroll
        for (int fn = 0; fn < 2; fn++) {
            wmma::load_matrix_sync(bh2[fn], &Kh[(wn * 32 + fn * 16) * 64 + kk], 64);
            wmma::load_matrix_sync(bl[fn],  &Kl[(wn * 32 + fn * 16) * 64 + kk], 64);
        }
#pragma unroll
        for (int fm = 0; fm < 4; fm++)
#pragma unroll
            for (int fn = 0; fn < 2; fn++) {
                wmma::mma_sync(acc[fm][fn], ah[fm], bh2[fn], acc[fm][fn]);
                wmma::mma_sync(acc[fm][fn], ah[fm], bl[fn],  acc[fm][fn]);
                wmma::mma_sync(acc[fm][fn], al[fm], bh2[fn], acc[fm][fn]);
            }
    }

    float* base = scores + (size_t)bh * S_ * S_;
#pragma unroll
    for (int fm = 0; fm < 4; fm++)
#pragma unroll
        for (int fn = 0; fn < 2; fn++)
            wmma::store_matrix_sync(
                base + (size_t)(q0 + wm * 64 + fm * 16) * S_ + (j0 + wn * 32 + fn * 16),
                acc[fm][fn], S_, wmma::mem_row_major);
}

// ---------------------------------------------------------------------------
// Softmax: one causal row per block. Writes zeros above diagonal.
// ---------------------------------------------------------------------------
__global__ void __launch_bounds__(256) softmax_kernel(float* __restrict__ attn)
{
    const int rowid = blockIdx.x;          // bh*S + q
    const int q = rowid & (S_ - 1);
    float* row = attn + (size_t)rowid * S_;

    const int tid = threadIdx.x;
    const int lane = tid & 31, wid = tid >> 5;
    __shared__ float red[8];
    __shared__ float bcast;

    float v[8];
    float m = -INFINITY;
#pragma unroll
    for (int t = 0; t < 8; t++) {
        int j = tid + t * 256;
        if (j <= q) { v[t] = row[j]; m = fmaxf(m, v[t]); }
    }
#pragma unroll
    for (int o = 16; o; o >>= 1) m = fmaxf(m, __shfl_xor_sync(0xffffffffu, m, o));
    if (lane == 0) red[wid] = m;
    __syncthreads();
    if (tid == 0) {
        float mm = red[0];
#pragma unroll
        for (int w = 1; w < 8; w++) mm = fmaxf(mm, red[w]);
        bcast = mm;
    }
    __syncthreads();
    m = bcast;

    float s = 0.f;
#pragma unroll
    for (int t = 0; t < 8; t++) {
        int j = tid + t * 256;
        if (j <= q) { v[t] = __expf(v[t] - m); s += v[t]; }
    }
#pragma unroll
    for (int o = 16; o; o >>= 1) s += __shfl_xor_sync(0xffffffffu, s, o);
    if (lane == 0) red[wid] = s;
    __syncthreads();
    if (tid == 0) {
        float ss = 0.f;
#pragma unroll
        for (int w = 0; w < 8; w++) ss += red[w];
        bcast = ss;
    }
    __syncthreads();
    const float inv = 1.0f / bcast;

#pragma unroll
    for (int t = 0; t < 8; t++) {
        int j = tid + t * 256;
        row[j] = (j <= q) ? v[t] * inv : 0.f;
    }
}

// ---------------------------------------------------------------------------
// PV, fp16x2: O_h[q,d] = sum_j P[q,j] V_h[j,d].
// Block = 128 q x 64 d (full head), BK=32 j-chunks, causal j skip.
// 24KB static smem -> high occupancy.
// ---------------------------------------------------------------------------
__global__ void __launch_bounds__(256) pv16(
    const float* __restrict__ attn, const float* __restrict__ Vp,
    float* __restrict__ O)
{
    const int qt = blockIdx.x;
    const int bh = blockIdx.y;
    const int b = bh >> 4;
    const int h = bh & 15;
    const int q0 = qt * 128;

    __shared__ __align__(128) __half Ph[128 * 32];
    __shared__ __align__(128) __half Pl[128 * 32];
    __shared__ __align__(128) __half Vh[32 * 64];
    __shared__ __align__(128) __half Vl[32 * 64];

    const int tid = threadIdx.x;
    const int w = tid >> 5;
    const int om = w >> 1;     // q offset om*32
    const int on = w & 1;      // d offset on*32

    HC acc[2][2];
#pragma unroll
    for (int fm = 0; fm < 2; fm++)
#pragma unroll
        for (int fn = 0; fn < 2; fn++) wmma::fill_fragment(acc[fm][fn], 0.0f);

    const float* arow = attn + (size_t)bh * S_ * S_;
    const int jmax = q0 + 128;       // P[q, j>q] == 0

    const int pr = tid >> 1;             // 0..127
    const int pc = (tid & 1) * 16;       // 0 or 16
    const int vr = tid >> 3;             // 0..31
    const int vc = (tid & 7) * 8;        // 0..56

    for (int j0 = 0; j0 < jmax; j0 += 32) {
        // P chunk 128x32
#pragma unroll
        for (int i = 0; i < 4; i++) {
            int c = pc + i * 4;
            float4 p4 = *(const float4*)&arow[(size_t)(q0 + pr) * S_ + j0 + c];
            int o = pr * 32 + c;
            split1(p4.x, &Ph[o + 0], &Pl[o + 0]);
            split1(p4.y, &Ph[o + 1], &Pl[o + 1]);
            split1(p4.z, &Ph[o + 2], &Pl[o + 2]);
            split1(p4.w, &Ph[o + 3], &Pl[o + 3]);
        }
        // V chunk 32x64
#pragma unroll
        for (int i = 0; i < 2; i++) {
            int c = vc + i * 4;
            float4 v4 = *(const float4*)&Vp[((size_t)b * S_ + j0 + vr) * E_ + h * DH_ + c];
            int o = vr * 64 + c;
            split1(v4.x, &Vh[o + 0], &Vl[o + 0]);
            split1(v4.y, &Vh[o + 1], &Vl[o + 1]);
            split1(v4.z, &Vh[o + 2], &Vl[o + 2]);
            split1(v4.w, &Vh[o + 3], &Vl[o + 3]);
        }
        __syncthreads();

#pragma unroll
        for (int ks = 0; ks < 2; ks++) {
            const int kk = ks * 16;
            HA pa[2], pl2[2];
            HBr vb[2], vl2[2];
#pragma unroll
            for (int fm = 0; fm < 2; fm++) {
                wmma::load_matrix_sync(pa[fm],  &Ph[(om * 32 + fm * 16) * 32 + kk], 32);
                wmma::load_matrix_sync(pl2[fm], &Pl[(om * 32 + fm * 16) * 32 + kk], 32);
            }
#pragma unroll
            for (int fn = 0; fn < 2; fn++) {
                wmma::load_matrix_sync(vb[fn],  &Vh[kk * 64 + on * 32 + fn * 16], 64);
                wmma::load_matrix_sync(vl2[fn], &Vl[kk * 64 + on * 32 + fn * 16], 64);
            }
#pragma unroll
            for (int fm = 0; fm < 2; fm++)
#pragma unroll
                for (int fn = 0; fn < 2; fn++) {
                    wmma::mma_sync(acc[fm][fn], pa[fm],  vb[fn],  acc[fm][fn]);
                    wmma::mma_sync(acc[fm][fn], pa[fm],  vl2[fn], acc[fm][fn]);
                    wmma::mma_sync(acc[fm][fn], pl2[fm], vb[fn],  acc[fm][fn]);
                }
        }
        __syncthreads();
    }

#pragma unroll
    for (int fm = 0; fm < 2; fm++)
#pragma unroll
        for (int fn = 0; fn < 2; fn++)
            wmma::store_matrix_sync(
                &O[((size_t)b * S_ + q0 + om * 32 + fm * 16) * E_ + h * DH_ + on * 32 + fn * 16],
                acc[fm][fn], E_, wmma::mem_row_major);
}

// ---------------------------------------------------------------------------
// Launch
// ---------------------------------------------------------------------------
extern "C" void kernel_launch(void* const* d_in, const int* in_sizes, int n_in,
                              void* d_out, int out_size)
{
    const float* q  = (const float*)d_in[0];
    const float* k  = (const float*)d_in[1];
    const float* v  = (const float*)d_in[2];
    const float* wq = (const float*)d_in[3];
    const float* bq = (const float*)d_in[4];
    const float* wk = (const float*)d_in[5];
    const float* bk = (const float*)d_in[6];
    const float* wv = (const float*)d_in[7];
    const float* bv = (const float*)d_in[8];
    const float* wo = (const float*)d_in[9];
    const float* bo = (const float*)d_in[10];

    float* out  = (float*)d_out;
    float* attn = (float*)d_out + OUT_ELEMS;

    float *gQ, *gK, *gV, *gO;
    cudaGetSymbolAddress((void**)&gQ, g_Q);
    cudaGetSymbolAddress((void**)&gK, g_K);
    cudaGetSymbolAddress((void**)&gV, g_V);
    cudaGetSymbolAddress((void**)&gO, g_O);

    cudaFuncSetAttribute(scores16, cudaFuncAttributeMaxDynamicSharedMemorySize, 65536);

    dim3 gproj(E_ / 128, M_ / 128);   // (8, 64)
    gemm_nt_fp16x2<<<gproj, 256>>>(q, wq, bq, gQ, M_, E_, E_);
    gemm_nt_fp16x2<<<gproj, 256>>>(k, wk, bk, gK, M_, E_, E_);
    gemm_nt_fp16x2<<<gproj, 256>>>(v, wv, bv, gV, M_, E_, E_);

    dim3 gsc(S_ / 128, S_ / 128, B_ * H_);  // (16, 16, 64)
    scores16<<<gsc, 256, 65536>>>(gQ, gK, attn);

    softmax_kernel<<<B_ * H_ * S_, 256>>>(attn);

    dim3 gpv(S_ / 128, B_ * H_);     // (16, 64)
    pv16<<<gpv, 256>>>(attn, gV, gO);

    gemm_nt_fp16x2<<<gproj, 256>>>(gO, wo, bo, out, M_, E_, E_);
}

// round 14
// speedup vs baseline: 2.2706x; 1.7330x over previous
#include <cuda_runtime.h>
#include <cuda_fp16.h>
#include <mma.h>
#include <math.h>

using namespace nvcuda;

// Problem constants
#define B_  4
#define S_  2048
#define E_  1024
#define H_  16
#define DH_ 64
#define M_  (B_ * S_)
#define OUT_ELEMS ((size_t)B_ * S_ * E_)

// Padded smem strides (in halfs) — chosen to break ldmatrix bank conflicts:
// 40 halfs = 80B = 20 words/row; 72 halfs = 144B = 36 words/row.
#define LDK 40    // for BK=32 tiles
#define LDD 72    // for 64-wide (head-dim / V) tiles

// Scratch (device globals: allocation-free per harness rules)
__device__ float g_Q[M_ * E_];
__device__ float g_K[M_ * E_];
__device__ float g_V[M_ * E_];
__device__ float g_O[M_ * E_];

typedef wmma::fragment<wmma::matrix_a, 16, 16, 16, __half, wmma::row_major> HA;
typedef wmma::fragment<wmma::matrix_b, 16, 16, 16, __half, wmma::col_major> HBc;
typedef wmma::fragment<wmma::matrix_b, 16, 16, 16, __half, wmma::row_major> HBr;
typedef wmma::fragment<wmma::accumulator, 16, 16, 16, float> HC;

// split fp32 x4 -> hi/lo fp16, packed __half2 stores (o must be even)
__device__ __forceinline__ void split_store4(
    float4 v, float scale, __half* h, __half* l, int o)
{
    float x0 = v.x * scale, x1 = v.y * scale, x2 = v.z * scale, x3 = v.w * scale;
    __half h0 = __float2half_rn(x0), h1 = __float2half_rn(x1);
    __half h2 = __float2half_rn(x2), h3 = __float2half_rn(x3);
    __half l0 = __float2half_rn(x0 - __half2float(h0));
    __half l1 = __float2half_rn(x1 - __half2float(h1));
    __half l2 = __float2half_rn(x2 - __half2float(h2));
    __half l3 = __float2half_rn(x3 - __half2float(h3));
    __half2* H = (__half2*)(h + o);
    __half2* L = (__half2*)(l + o);
    H[0] = __halves2half2(h0, h1); H[1] = __halves2half2(h2, h3);
    L[0] = __halves2half2(l0, l1); L[1] = __halves2half2(l2, l3);
}

// ---------------------------------------------------------------------------
// NT GEMM, fp16x2 compensated: C[M,N] = A[M,K] @ W[N,K]^T + bias[N]
// BM=BN=128, BK=32, 256 threads = 8 warps (2x4), warp tile 64x32.
// Padded stride LDK=40 kills ldmatrix bank conflicts.
// ---------------------------------------------------------------------------
__global__ void __launch_bounds__(256) gemm_nt_fp16x2(
    const float* __restrict__ A, const float* __restrict__ W,
    const float* __restrict__ bias, float* __restrict__ C,
    int Mdim, int Ndim, int Kdim)
{
    __shared__ __align__(128) __half Ah[128 * LDK];
    __shared__ __align__(128) __half Al[128 * LDK];
    __shared__ __align__(128) __half Bh[128 * LDK];
    __shared__ __align__(128) __half Bl[128 * LDK];

    const int tid = threadIdx.x;
    const int w = tid >> 5, lane = tid & 31;
    const int m0 = blockIdx.y * 128, n0 = blockIdx.x * 128;
    const int wm = w & 1;     // rows wm*64
    const int wn = w >> 1;    // cols wn*32

    HC acc[4][2];
#pragma unroll
    for (int fm = 0; fm < 4; fm++)
#pragma unroll
        for (int fn = 0; fn < 2; fn++) wmma::fill_fragment(acc[fm][fn], 0.0f);

    const int r = tid >> 1;
    const int cb = (tid & 1) * 16;

    for (int k0 = 0; k0 < Kdim; k0 += 32) {
#pragma unroll
        for (int i = 0; i < 4; i++) {
            int c = cb + i * 4;
            int o = r * LDK + c;
            split_store4(*(const float4*)&A[(size_t)(m0 + r) * Kdim + k0 + c],
                         1.0f, Ah, Al, o);
            split_store4(*(const float4*)&W[(size_t)(n0 + r) * Kdim + k0 + c],
                         1.0f, Bh, Bl, o);
        }
        __syncthreads();

#pragma unroll
        for (int ks = 0; ks < 2; ks++) {
            const int kk = ks * 16;
            HA ah[4], al[4];
            HBc bh[2], bl[2];
#pragma unroll
            for (int fm = 0; fm < 4; fm++) {
                wmma::load_matrix_sync(ah[fm], &Ah[(wm * 64 + fm * 16) * LDK + kk], LDK);
                wmma::load_matrix_sync(al[fm], &Al[(wm * 64 + fm * 16) * LDK + kk], LDK);
            }
#pragma unroll
            for (int fn = 0; fn < 2; fn++) {
                wmma::load_matrix_sync(bh[fn], &Bh[(wn * 32 + fn * 16) * LDK + kk], LDK);
                wmma::load_matrix_sync(bl[fn], &Bl[(wn * 32 + fn * 16) * LDK + kk], LDK);
            }
#pragma unroll
            for (int fm = 0; fm < 4; fm++)
#pragma unroll
                for (int fn = 0; fn < 2; fn++) {
                    wmma::mma_sync(acc[fm][fn], ah[fm], bh[fn], acc[fm][fn]);
                    wmma::mma_sync(acc[fm][fn], ah[fm], bl[fn], acc[fm][fn]);
                    wmma::mma_sync(acc[fm][fn], al[fm], bh[fn], acc[fm][fn]);
                }
        }
        __syncthreads();
    }

    // Epilogue: stage through (now-dead) Ah region, add bias, float4 stores.
    float* stage = (float*)Ah;          // 8 warps x 256 floats = 8KB < |Ah|
    float* mystage = stage + w * 256;
    const int er = lane >> 1;
    const int ec = (lane & 1) * 8;
#pragma unroll
    for (int fm = 0; fm < 4; fm++)
#pragma unroll
        for (int fn = 0; fn < 2; fn++) {
            wmma::store_matrix_sync(mystage, acc[fm][fn], 16, wmma::mem_row_major);
            __syncwarp();
            int gm = m0 + wm * 64 + fm * 16 + er;
            int gn = n0 + wn * 32 + fn * 16 + ec;
            float4 s0 = *(float4*)&mystage[er * 16 + ec];
            float4 s1 = *(float4*)&mystage[er * 16 + ec + 4];
            float4 b0 = *(const float4*)&bias[gn];
            float4 b1 = *(const float4*)&bias[gn + 4];
            s0.x += b0.x; s0.y += b0.y; s0.z += b0.z; s0.w += b0.w;
            s1.x += b1.x; s1.y += b1.y; s1.z += b1.z; s1.w += b1.w;
            *(float4*)&C[(size_t)gm * Ndim + gn]     = s0;
            *(float4*)&C[(size_t)gm * Ndim + gn + 4] = s1;
            __syncwarp();
        }
}

// ---------------------------------------------------------------------------
// Load 128x64 fp32 head-slice, scale, split into hi/lo (stride LDD=72).
// ---------------------------------------------------------------------------
__device__ __forceinline__ void load_split_128x64(
    const float* __restrict__ src, float scale, __half* h, __half* l, int tid)
{
    const int r = tid >> 1, cb = (tid & 1) * 32;
    const float* row = src + (size_t)r * E_ + cb;
#pragma unroll
    for (int i = 0; i < 8; i++) {
        split_store4(*(const float4*)(row + i * 4), scale, h, l,
                     r * LDD + cb + i * 4);
    }
}

// ---------------------------------------------------------------------------
// Scores, fp16x2: raw S[q,j] = (Q*0.125) . K, 128x128 tile, causal tile skip.
// Dynamic smem 4 * 128*72*2 = 73728 B -> 3 CTAs/SM.
// ---------------------------------------------------------------------------
#define SC_SMEM (4 * 128 * LDD * 2)
__global__ void __launch_bounds__(256) scores16(
    const float* __restrict__ Qp, const float* __restrict__ Kp,
    float* __restrict__ scores)
{
    const int jt = blockIdx.x;
    const int qt = blockIdx.y;
    if (jt > qt) return;
    const int bh = blockIdx.z;
    const int b = bh >> 4;
    const int h = bh & 15;
    const int q0 = qt * 128, j0 = jt * 128;

    extern __shared__ __align__(128) char sm[];
    __half* Qh = (__half*)sm;
    __half* Ql = (__half*)(sm + 128 * LDD * 2);
    __half* Kh = (__half*)(sm + 2 * 128 * LDD * 2);
    __half* Kl = (__half*)(sm + 3 * 128 * LDD * 2);

    const int tid = threadIdx.x;
    const int w = tid >> 5;
    const int wm = w & 1, wn = w >> 1;

    load_split_128x64(Qp + ((size_t)b * S_ + q0) * E_ + h * DH_, 0.125f, Qh, Ql, tid);
    load_split_128x64(Kp + ((size_t)b * S_ + j0) * E_ + h * DH_, 1.0f,  Kh, Kl, tid);
    __syncthreads();

    HC acc[4][2];
#pragma unroll
    for (int fm = 0; fm < 4; fm++)
#pragma unroll
        for (int fn = 0; fn < 2; fn++) wmma::fill_fragment(acc[fm][fn], 0.0f);

#pragma unroll
    for (int ks = 0; ks < 4; ks++) {
        const int kk = ks * 16;
        HA ah[4], al[4];
        HBc bh2[2], bl[2];
#pragma unroll
        for (int fm = 0; fm < 4; fm++) {
            wmma::load_matrix_sync(ah[fm], &Qh[(wm * 64 + fm * 16) * LDD + kk], LDD);
            wmma::load_matrix_sync(al[fm], &Ql[(wm * 64 + fm * 16) * LDD + kk], LDD);
        }
#pragma unroll
        for (int fn = 0; fn < 2; fn++) {
            wmma::load_matrix_sync(bh2[fn], &Kh[(wn * 32 + fn * 16) * LDD + kk], LDD);
            wmma::load_matrix_sync(bl[fn],  &Kl[(wn * 32 + fn * 16) * LDD + kk], LDD);
        }
#pragma unroll
        for (int fm = 0; fm < 4; fm++)
#pragma unroll
            for (int fn = 0; fn < 2; fn++) {
                wmma::mma_sync(acc[fm][fn], ah[fm], bh2[fn], acc[fm][fn]);
                wmma::mma_sync(acc[fm][fn], ah[fm], bl[fn],  acc[fm][fn]);
                wmma::mma_sync(acc[fm][fn], al[fm], bh2[fn], acc[fm][fn]);
            }
    }

    float* base = scores + (size_t)bh * S_ * S_;
#pragma unroll
    for (int fm = 0; fm < 4; fm++)
#pragma unroll
        for (int fn = 0; fn < 2; fn++)
            wmma::store_matrix_sync(
                base + (size_t)(q0 + wm * 64 + fm * 16) * S_ + (j0 + wn * 32 + fn * 16),
                acc[fm][fn], S_, wmma::mem_row_major);
}

// ---------------------------------------------------------------------------
// Softmax: one causal row per block. Writes zeros above diagonal.
// ---------------------------------------------------------------------------
__global__ void __launch_bounds__(256) softmax_kernel(float* __restrict__ attn)
{
    const int rowid = blockIdx.x;          // bh*S + q
    const int q = rowid & (S_ - 1);
    float* row = attn + (size_t)rowid * S_;

    const int tid = threadIdx.x;
    const int lane = tid & 31, wid = tid >> 5;
    __shared__ float red[8];
    __shared__ float bcast;

    float v[8];
    float m = -INFINITY;
#pragma unroll
    for (int t = 0; t < 8; t++) {
        int j = tid + t * 256;
        if (j <= q) { v[t] = row[j]; m = fmaxf(m, v[t]); }
    }
#pragma unroll
    for (int o = 16; o; o >>= 1) m = fmaxf(m, __shfl_xor_sync(0xffffffffu, m, o));
    if (lane == 0) red[wid] = m;
    __syncthreads();
    if (tid == 0) {
        float mm = red[0];
#pragma unroll
        for (int w = 1; w < 8; w++) mm = fmaxf(mm, red[w]);
        bcast = mm;
    }
    __syncthreads();
    m = bcast;

    float s = 0.f;
#pragma unroll
    for (int t = 0; t < 8; t++) {
        int j = tid + t * 256;
        if (j <= q) { v[t] = __expf(v[t] - m); s += v[t]; }
    }
#pragma unroll
    for (int o = 16; o; o >>= 1) s += __shfl_xor_sync(0xffffffffu, s, o);
    if (lane == 0) red[wid] = s;
    __syncthreads();
    if (tid == 0) {
        float ss = 0.f;
#pragma unroll
        for (int w = 0; w < 8; w++) ss += red[w];
        bcast = ss;
    }
    __syncthreads();
    const float inv = 1.0f / bcast;

#pragma unroll
    for (int t = 0; t < 8; t++) {
        int j = tid + t * 256;
        row[j] = (j <= q) ? v[t] * inv : 0.f;
    }
}

// ---------------------------------------------------------------------------
// PV, fp16x2: O_h[q,d] = sum_j P[q,j] V_h[j,d].
// Block = 128 q x 64 d, BK=32 j-chunks, causal j skip. Padded strides.
// ---------------------------------------------------------------------------
__global__ void __launch_bounds__(256) pv16(
    const float* __restrict__ attn, const float* __restrict__ Vp,
    float* __restrict__ O)
{
    const int qt = blockIdx.x;
    const int bh = blockIdx.y;
    const int b = bh >> 4;
    const int h = bh & 15;
    const int q0 = qt * 128;

    __shared__ __align__(128) __half Ph[128 * LDK];
    __shared__ __align__(128) __half Pl[128 * LDK];
    __shared__ __align__(128) __half Vh[32 * LDD];
    __shared__ __align__(128) __half Vl[32 * LDD];

    const int tid = threadIdx.x;
    const int w = tid >> 5;
    const int om = w >> 1;     // q offset om*32
    const int on = w & 1;      // d offset on*32

    HC acc[2][2];
#pragma unroll
    for (int fm = 0; fm < 2; fm++)
#pragma unroll
        for (int fn = 0; fn < 2; fn++) wmma::fill_fragment(acc[fm][fn], 0.0f);

    const float* arow = attn + (size_t)bh * S_ * S_;
    const int jmax = q0 + 128;       // P[q, j>q] == 0

    const int pr = tid >> 1;             // 0..127
    const int pc = (tid & 1) * 16;       // 0 or 16
    const int vr = tid >> 3;             // 0..31
    const int vc = (tid & 7) * 8;        // 0..56

    for (int j0 = 0; j0 < jmax; j0 += 32) {
#pragma unroll
        for (int i = 0; i < 4; i++) {
            int c = pc + i * 4;
            split_store4(*(const float4*)&arow[(size_t)(q0 + pr) * S_ + j0 + c],
                         1.0f, Ph, Pl, pr * LDK + c);
        }
#pragma unroll
        for (int i = 0; i < 2; i++) {
            int c = vc + i * 4;
            split_store4(*(const float4*)&Vp[((size_t)b * S_ + j0 + vr) * E_ + h * DH_ + c],
                         1.0f, Vh, Vl, vr * LDD + c);
        }
        __syncthreads();

#pragma unroll
        for (int ks = 0; ks < 2; ks++) {
            const int kk = ks * 16;
            HA pa[2], pl2[2];
            HBr vb[2], vl2[2];
#pragma unroll
            for (int fm = 0; fm < 2; fm++) {
                wmma::load_matrix_sync(pa[fm],  &Ph[(om * 32 + fm * 16) * LDK + kk], LDK);
                wmma::load_matrix_sync(pl2[fm], &Pl[(om * 32 + fm * 16) * LDK + kk], LDK);
            }
#pragma unroll
            for (int fn = 0; fn < 2; fn++) {
                wmma::load_matrix_sync(vb[fn],  &Vh[kk * LDD + on * 32 + fn * 16], LDD);
                wmma::load_matrix_sync(vl2[fn], &Vl[kk * LDD + on * 32 + fn * 16], LDD);
            }
#pragma unroll
            for (int fm = 0; fm < 2; fm++)
#pragma unroll
                for (int fn = 0; fn < 2; fn++) {
                    wmma::mma_sync(acc[fm][fn], pa[fm],  vb[fn],  acc[fm][fn]);
                    wmma::mma_sync(acc[fm][fn], pa[fm],  vl2[fn], acc[fm][fn]);
                    wmma::mma_sync(acc[fm][fn], pl2[fm], vb[fn],  acc[fm][fn]);
                }
        }
        __syncthreads();
    }

#pragma unroll
    for (int fm = 0; fm < 2; fm++)
#pragma unroll
        for (int fn = 0; fn < 2; fn++)
            wmma::store_matrix_sync(
                &O[((size_t)b * S_ + q0 + om * 32 + fm * 16) * E_ + h * DH_ + on * 32 + fn * 16],
                acc[fm][fn], E_, wmma::mem_row_major);
}

// ---------------------------------------------------------------------------
// Launch
// ---------------------------------------------------------------------------
extern "C" void kernel_launch(void* const* d_in, const int* in_sizes, int n_in,
                              void* d_out, int out_size)
{
    const float* q  = (const float*)d_in[0];
    const float* k  = (const float*)d_in[1];
    const float* v  = (const float*)d_in[2];
    const float* wq = (const float*)d_in[3];
    const float* bq = (const float*)d_in[4];
    const float* wk = (const float*)d_in[5];
    const float* bk = (const float*)d_in[6];
    const float* wv = (const float*)d_in[7];
    const float* bv = (const float*)d_in[8];
    const float* wo = (const float*)d_in[9];
    const float* bo = (const float*)d_in[10];

    float* out  = (float*)d_out;
    float* attn = (float*)d_out + OUT_ELEMS;

    float *gQ, *gK, *gV, *gO;
    cudaGetSymbolAddress((void**)&gQ, g_Q);
    cudaGetSymbolAddress((void**)&gK, g_K);
    cudaGetSymbolAddress((void**)&gV, g_V);
    cudaGetSymbolAddress((void**)&gO, g_O);

    cudaFuncSetAttribute(scores16, cudaFuncAttributeMaxDynamicSharedMemorySize, SC_SMEM);

    dim3 gproj(E_ / 128, M_ / 128);   // (8, 64)
    gemm_nt_fp16x2<<<gproj, 256>>>(q, wq, bq, gQ, M_, E_, E_);
    gemm_nt_fp16x2<<<gproj, 256>>>(k, wk, bk, gK, M_, E_, E_);
    gemm_nt_fp16x2<<<gproj, 256>>>(v, wv, bv, gV, M_, E_, E_);

    dim3 gsc(S_ / 128, S_ / 128, B_ * H_);  // (16, 16, 64)
    scores16<<<gsc, 256, SC_SMEM>>>(gQ, gK, attn);

    softmax_kernel<<<B_ * H_ * S_, 256>>>(attn);

    dim3 gpv(S_ / 128, B_ * H_);     // (16, 64)
    pv16<<<gpv, 256>>>(attn, gV, gO);

    gemm_nt_fp16x2<<<gproj, 256>>>(gO, wo, bo, out, M_, E_, E_);
}